// round 1
// baseline (speedup 1.0000x reference)
#include <cuda_runtime.h>
#include <math.h>

// Problem constants (fixed by the dataset)
#define NNODES 50000
#define HDIM   768
#define D1DIM  256
#define NOUT   512        // 2*D1: [A | B] per node
#define NEDGES 200000
#define NCLS   2

// GEMM tiling
#define BM 128
#define BN 128
#define BK 16

#define EDGE_WARPS 8                       // warps (edges) per block
#define EDGE_BLOCKS (NEDGES / EDGE_WARPS)  // 25000

// Scratch (static device globals; no runtime allocation)
__device__ float g_AB[(size_t)NNODES * NOUT];        // ~102.4 MB
__device__ float g_partials[2 * EDGE_BLOCKS];

// ---------------------------------------------------------------------------
// Kernel 1: AB = x @ Wcat   (x: [N,768] row-major, W1: [256,1536] row-major)
//   AB[n, j]       = sum_k x[n,k] * W1[j, k]        (j <  256)
//   AB[n, 256+j]   = sum_k x[n,k] * W1[j, 768+k]    (j >= 256 part)
// Classic 128x128x16 fp32 SGEMM, 256 threads, 8x8 per thread.
// ---------------------------------------------------------------------------
__global__ __launch_bounds__(256) void gemm_kernel(const float* __restrict__ x,
                                                   const float* __restrict__ W1)
{
    __shared__ float As[BK][BM];
    __shared__ float Bs[BK][BN];

    const int tid = threadIdx.x;
    const int m0  = blockIdx.x * BM;
    const int n0  = blockIdx.y * BN;

    // Which half of Wcat this n-block maps to (BN=128 never straddles D1=256)
    const float* Wbase = (n0 < D1DIM)
        ? (W1 + (size_t)n0 * (2 * HDIM))
        : (W1 + (size_t)(n0 - D1DIM) * (2 * HDIM) + HDIM);

    const int tx = tid & 15;          // 0..15  -> n sub-tile
    const int ty = tid >> 4;          // 0..15  -> m sub-tile

    float acc[8][8];
    #pragma unroll
    for (int i = 0; i < 8; i++)
        #pragma unroll
        for (int j = 0; j < 8; j++) acc[i][j] = 0.f;

    for (int kt = 0; kt < HDIM; kt += BK) {
        // --- load A tile: 128 rows x 16 k = 512 float4, 2 per thread ---
        #pragma unroll
        for (int l = 0; l < 2; l++) {
            int fi  = tid + l * 256;          // 0..511
            int row = fi >> 2;                // 0..127
            int kv  = fi & 3;                 // 0..3 (float4 within 16 k)
            int gm  = m0 + row;
            float4 v = make_float4(0.f, 0.f, 0.f, 0.f);
            if (gm < NNODES)
                v = *(const float4*)(x + (size_t)gm * HDIM + kt + kv * 4);
            As[kv * 4 + 0][row] = v.x;
            As[kv * 4 + 1][row] = v.y;
            As[kv * 4 + 2][row] = v.z;
            As[kv * 4 + 3][row] = v.w;
        }
        // --- load B tile: 128 rows x 16 k ---
        #pragma unroll
        for (int l = 0; l < 2; l++) {
            int fi  = tid + l * 256;
            int row = fi >> 2;
            int kv  = fi & 3;
            float4 v = *(const float4*)(Wbase + (size_t)row * (2 * HDIM) + kt + kv * 4);
            Bs[kv * 4 + 0][row] = v.x;
            Bs[kv * 4 + 1][row] = v.y;
            Bs[kv * 4 + 2][row] = v.z;
            Bs[kv * 4 + 3][row] = v.w;
        }
        __syncthreads();

        #pragma unroll
        for (int kk = 0; kk < BK; kk++) {
            float4 a0 = *(const float4*)&As[kk][ty * 8];
            float4 a1 = *(const float4*)&As[kk][ty * 8 + 4];
            float4 b0 = *(const float4*)&Bs[kk][tx * 8];
            float4 b1 = *(const float4*)&Bs[kk][tx * 8 + 4];
            float ra[8] = {a0.x, a0.y, a0.z, a0.w, a1.x, a1.y, a1.z, a1.w};
            float rb[8] = {b0.x, b0.y, b0.z, b0.w, b1.x, b1.y, b1.z, b1.w};
            #pragma unroll
            for (int i = 0; i < 8; i++)
                #pragma unroll
                for (int j = 0; j < 8; j++)
                    acc[i][j] = fmaf(ra[i], rb[j], acc[i][j]);
        }
        __syncthreads();
    }

    // --- store ---
    #pragma unroll
    for (int i = 0; i < 8; i++) {
        int gm = m0 + ty * 8 + i;
        if (gm < NNODES) {
            float* dst = g_AB + (size_t)gm * NOUT + n0 + tx * 8;
            *(float4*)(dst)     = make_float4(acc[i][0], acc[i][1], acc[i][2], acc[i][3]);
            *(float4*)(dst + 4) = make_float4(acc[i][4], acc[i][5], acc[i][6], acc[i][7]);
        }
    }
}

// ---------------------------------------------------------------------------
// Kernel 2: per-edge MLP tail. One warp per edge.
//   h[j]   = gelu(AB[src, j] + AB[dst, 256+j] + b1[j])       (exact erf gelu)
//   logits = h @ W2^T + b2 ; softmax ; probs out ; weighted NLL partials
// ---------------------------------------------------------------------------
__global__ __launch_bounds__(256) void edge_kernel(const float* __restrict__ b1,
                                                   const float* __restrict__ W2,
                                                   const float* __restrict__ b2,
                                                   const float* __restrict__ cw,
                                                   const int* __restrict__ esrc,
                                                   const int* __restrict__ edst,
                                                   const int* __restrict__ labels,
                                                   float* __restrict__ out)
{
    __shared__ float s_b1[D1DIM];
    __shared__ float s_W2[2 * D1DIM];
    __shared__ float s_wn[EDGE_WARPS];
    __shared__ float s_w[EDGE_WARPS];

    const int tid  = threadIdx.x;
    const int lane = tid & 31;
    const int warp = tid >> 5;

    if (tid < D1DIM) s_b1[tid] = b1[tid];
    s_W2[tid]       = W2[tid];
    s_W2[tid + 256] = W2[tid + 256];
    __syncthreads();

    const int edge = blockIdx.x * EDGE_WARPS + warp;

    float acc0 = 0.f, acc1 = 0.f;
    if (edge < NEDGES) {
        const int s = esrc[edge];
        const int d = edst[edge];
        const float* pa = g_AB + (size_t)s * NOUT;           // A half
        const float* pb = g_AB + (size_t)d * NOUT + D1DIM;   // B half
        #pragma unroll
        for (int i = 0; i < D1DIM / 32; i++) {
            const int j = lane + i * 32;
            float v = pa[j] + pb[j] + s_b1[j];
            float h = 0.5f * v * (1.0f + erff(v * 0.70710678118654752f));
            acc0 = fmaf(h, s_W2[j], acc0);
            acc1 = fmaf(h, s_W2[256 + j], acc1);
        }
    }
    #pragma unroll
    for (int o = 16; o > 0; o >>= 1) {
        acc0 += __shfl_xor_sync(0xFFFFFFFFu, acc0, o);
        acc1 += __shfl_xor_sync(0xFFFFFFFFu, acc1, o);
    }

    float wn = 0.f, wsum = 0.f;
    if (lane == 0 && edge < NEDGES) {
        const float l0 = acc0 + __ldg(&b2[0]);
        const float l1 = acc1 + __ldg(&b2[1]);
        const float m  = fmaxf(l0, l1);
        const float e0 = expf(l0 - m);
        const float e1 = expf(l1 - m);
        const float ssum = e0 + e1;
        const float inv  = 1.0f / ssum;
        out[1 + 2 * edge]     = e0 * inv;     // probs (after loss scalar at out[0])
        out[1 + 2 * edge + 1] = e1 * inv;
        const int lb  = labels[edge];
        const float ll   = lb ? l1 : l0;
        const float logp = (ll - m) - logf(ssum);
        const float w    = __ldg(&cw[lb]);
        wn   = -w * logp;
        wsum = w;
    }
    if (lane == 0) { s_wn[warp] = wn; s_w[warp] = wsum; }
    __syncthreads();
    if (tid == 0) {
        float a = 0.f, b = 0.f;
        #pragma unroll
        for (int i = 0; i < EDGE_WARPS; i++) { a += s_wn[i]; b += s_w[i]; }
        g_partials[blockIdx.x]               = a;
        g_partials[EDGE_BLOCKS + blockIdx.x] = b;
    }
}

// ---------------------------------------------------------------------------
// Kernel 3: deterministic final reduction -> loss at out[0]
// ---------------------------------------------------------------------------
__global__ __launch_bounds__(256) void finalize_kernel(float* __restrict__ out)
{
    __shared__ float sa[256];
    __shared__ float sb[256];
    const int tid = threadIdx.x;
    float a = 0.f, b = 0.f;
    for (int i = tid; i < EDGE_BLOCKS; i += 256) {
        a += g_partials[i];
        b += g_partials[EDGE_BLOCKS + i];
    }
    sa[tid] = a; sb[tid] = b;
    __syncthreads();
    for (int o = 128; o > 0; o >>= 1) {
        if (tid < o) { sa[tid] += sa[tid + o]; sb[tid] += sb[tid + o]; }
        __syncthreads();
    }
    if (tid == 0) out[0] = sa[0] / sb[0];
}

// ---------------------------------------------------------------------------
extern "C" void kernel_launch(void* const* d_in, const int* in_sizes, int n_in,
                              void* d_out, int out_size)
{
    const float* x      = (const float*)d_in[0];
    const float* W1     = (const float*)d_in[1];
    const float* b1     = (const float*)d_in[2];
    const float* W2     = (const float*)d_in[3];
    const float* b2     = (const float*)d_in[4];
    const float* cw     = (const float*)d_in[5];
    const int*   esrc   = (const int*)d_in[6];
    const int*   edst   = (const int*)d_in[7];
    const int*   labels = (const int*)d_in[8];
    float* out = (float*)d_out;

    dim3 ggrid((NNODES + BM - 1) / BM, NOUT / BN);   // 391 x 4
    gemm_kernel<<<ggrid, 256>>>(x, W1);
    edge_kernel<<<EDGE_BLOCKS, 256>>>(b1, W2, b2, cw, esrc, edst, labels, out);
    finalize_kernel<<<1, 256>>>(out);
}

// round 2
// speedup vs baseline: 1.0015x; 1.0015x over previous
#include <cuda_runtime.h>
#include <math.h>

// Problem constants (fixed by the dataset)
#define NNODES 50000
#define HDIM   768
#define D1DIM  256
#define NOUT   512        // 2*D1: [A | B] per node
#define NEDGES 200000
#define NCLS   2

// GEMM tiling
#define BM 128
#define BN 128
#define BK 16

#define EDGE_WARPS 8                       // warps (edges) per block
#define EDGE_BLOCKS (NEDGES / EDGE_WARPS)  // 25000

// Scratch (static device globals; no runtime allocation)
__device__ float g_AB[(size_t)NNODES * NOUT];        // ~102.4 MB
__device__ float g_partials[2 * EDGE_BLOCKS];

// ---------------------------------------------------------------------------
// Kernel 1: AB = x @ Wcat   (x: [N,768] row-major, W1: [256,1536] row-major)
//   AB[n, j]       = sum_k x[n,k] * W1[j, k]        (j <  256)
//   AB[n, 256+j]   = sum_k x[n,k] * W1[j, 768+k]    (j >= 256 part)
// Classic 128x128x16 fp32 SGEMM, 256 threads, 8x8 per thread.
// ---------------------------------------------------------------------------
__global__ __launch_bounds__(256) void gemm_kernel(const float* __restrict__ x,
                                                   const float* __restrict__ W1)
{
    __shared__ float As[BK][BM];
    __shared__ float Bs[BK][BN];

    const int tid = threadIdx.x;
    const int m0  = blockIdx.x * BM;
    const int n0  = blockIdx.y * BN;

    // Which half of Wcat this n-block maps to (BN=128 never straddles D1=256)
    const float* Wbase = (n0 < D1DIM)
        ? (W1 + (size_t)n0 * (2 * HDIM))
        : (W1 + (size_t)(n0 - D1DIM) * (2 * HDIM) + HDIM);

    const int tx = tid & 15;          // 0..15  -> n sub-tile
    const int ty = tid >> 4;          // 0..15  -> m sub-tile

    float acc[8][8];
    #pragma unroll
    for (int i = 0; i < 8; i++)
        #pragma unroll
        for (int j = 0; j < 8; j++) acc[i][j] = 0.f;

    for (int kt = 0; kt < HDIM; kt += BK) {
        // --- load A tile: 128 rows x 16 k = 512 float4, 2 per thread ---
        #pragma unroll
        for (int l = 0; l < 2; l++) {
            int fi  = tid + l * 256;          // 0..511
            int row = fi >> 2;                // 0..127
            int kv  = fi & 3;                 // 0..3 (float4 within 16 k)
            int gm  = m0 + row;
            float4 v = make_float4(0.f, 0.f, 0.f, 0.f);
            if (gm < NNODES)
                v = *(const float4*)(x + (size_t)gm * HDIM + kt + kv * 4);
            As[kv * 4 + 0][row] = v.x;
            As[kv * 4 + 1][row] = v.y;
            As[kv * 4 + 2][row] = v.z;
            As[kv * 4 + 3][row] = v.w;
        }
        // --- load B tile: 128 rows x 16 k ---
        #pragma unroll
        for (int l = 0; l < 2; l++) {
            int fi  = tid + l * 256;
            int row = fi >> 2;
            int kv  = fi & 3;
            float4 v = *(const float4*)(Wbase + (size_t)row * (2 * HDIM) + kt + kv * 4);
            Bs[kv * 4 + 0][row] = v.x;
            Bs[kv * 4 + 1][row] = v.y;
            Bs[kv * 4 + 2][row] = v.z;
            Bs[kv * 4 + 3][row] = v.w;
        }
        __syncthreads();

        #pragma unroll
        for (int kk = 0; kk < BK; kk++) {
            float4 a0 = *(const float4*)&As[kk][ty * 8];
            float4 a1 = *(const float4*)&As[kk][ty * 8 + 4];
            float4 b0 = *(const float4*)&Bs[kk][tx * 8];
            float4 b1 = *(const float4*)&Bs[kk][tx * 8 + 4];
            float ra[8] = {a0.x, a0.y, a0.z, a0.w, a1.x, a1.y, a1.z, a1.w};
            float rb[8] = {b0.x, b0.y, b0.z, b0.w, b1.x, b1.y, b1.z, b1.w};
            #pragma unroll
            for (int i = 0; i < 8; i++)
                #pragma unroll
                for (int j = 0; j < 8; j++)
                    acc[i][j] = fmaf(ra[i], rb[j], acc[i][j]);
        }
        __syncthreads();
    }

    // --- store ---
    #pragma unroll
    for (int i = 0; i < 8; i++) {
        int gm = m0 + ty * 8 + i;
        if (gm < NNODES) {
            float* dst = g_AB + (size_t)gm * NOUT + n0 + tx * 8;
            *(float4*)(dst)     = make_float4(acc[i][0], acc[i][1], acc[i][2], acc[i][3]);
            *(float4*)(dst + 4) = make_float4(acc[i][4], acc[i][5], acc[i][6], acc[i][7]);
        }
    }
}

// ---------------------------------------------------------------------------
// Kernel 2: per-edge MLP tail. One warp per edge.
//   h[j]   = gelu(AB[src, j] + AB[dst, 256+j] + b1[j])       (exact erf gelu)
//   logits = h @ W2^T + b2 ; softmax ; probs out ; weighted NLL partials
// ---------------------------------------------------------------------------
__global__ __launch_bounds__(256) void edge_kernel(const float* __restrict__ b1,
                                                   const float* __restrict__ W2,
                                                   const float* __restrict__ b2,
                                                   const float* __restrict__ cw,
                                                   const int* __restrict__ esrc,
                                                   const int* __restrict__ edst,
                                                   const int* __restrict__ labels,
                                                   float* __restrict__ out)
{
    __shared__ float s_b1[D1DIM];
    __shared__ float s_W2[2 * D1DIM];
    __shared__ float s_wn[EDGE_WARPS];
    __shared__ float s_w[EDGE_WARPS];

    const int tid  = threadIdx.x;
    const int lane = tid & 31;
    const int warp = tid >> 5;

    if (tid < D1DIM) s_b1[tid] = b1[tid];
    s_W2[tid]       = W2[tid];
    s_W2[tid + 256] = W2[tid + 256];
    __syncthreads();

    const int edge = blockIdx.x * EDGE_WARPS + warp;

    float acc0 = 0.f, acc1 = 0.f;
    if (edge < NEDGES) {
        const int s = esrc[edge];
        const int d = edst[edge];
        const float* pa = g_AB + (size_t)s * NOUT;           // A half
        const float* pb = g_AB + (size_t)d * NOUT + D1DIM;   // B half
        #pragma unroll
        for (int i = 0; i < D1DIM / 32; i++) {
            const int j = lane + i * 32;
            float v = pa[j] + pb[j] + s_b1[j];
            float h = 0.5f * v * (1.0f + erff(v * 0.70710678118654752f));
            acc0 = fmaf(h, s_W2[j], acc0);
            acc1 = fmaf(h, s_W2[256 + j], acc1);
        }
    }
    #pragma unroll
    for (int o = 16; o > 0; o >>= 1) {
        acc0 += __shfl_xor_sync(0xFFFFFFFFu, acc0, o);
        acc1 += __shfl_xor_sync(0xFFFFFFFFu, acc1, o);
    }

    float wn = 0.f, wsum = 0.f;
    if (lane == 0 && edge < NEDGES) {
        const float l0 = acc0 + __ldg(&b2[0]);
        const float l1 = acc1 + __ldg(&b2[1]);
        const float m  = fmaxf(l0, l1);
        const float e0 = expf(l0 - m);
        const float e1 = expf(l1 - m);
        const float ssum = e0 + e1;
        const float inv  = 1.0f / ssum;
        out[1 + 2 * edge]     = e0 * inv;     // probs (after loss scalar at out[0])
        out[1 + 2 * edge + 1] = e1 * inv;
        const int lb  = labels[edge];
        const float ll   = lb ? l1 : l0;
        const float logp = (ll - m) - logf(ssum);
        const float w    = __ldg(&cw[lb]);
        wn   = -w * logp;
        wsum = w;
    }
    if (lane == 0) { s_wn[warp] = wn; s_w[warp] = wsum; }
    __syncthreads();
    if (tid == 0) {
        float a = 0.f, b = 0.f;
        #pragma unroll
        for (int i = 0; i < EDGE_WARPS; i++) { a += s_wn[i]; b += s_w[i]; }
        g_partials[blockIdx.x]               = a;
        g_partials[EDGE_BLOCKS + blockIdx.x] = b;
    }
}

// ---------------------------------------------------------------------------
// Kernel 3: deterministic final reduction -> loss at out[0]
// ---------------------------------------------------------------------------
__global__ __launch_bounds__(256) void finalize_kernel(float* __restrict__ out)
{
    __shared__ float sa[256];
    __shared__ float sb[256];
    const int tid = threadIdx.x;
    float a = 0.f, b = 0.f;
    for (int i = tid; i < EDGE_BLOCKS; i += 256) {
        a += g_partials[i];
        b += g_partials[EDGE_BLOCKS + i];
    }
    sa[tid] = a; sb[tid] = b;
    __syncthreads();
    for (int o = 128; o > 0; o >>= 1) {
        if (tid < o) { sa[tid] += sa[tid + o]; sb[tid] += sb[tid + o]; }
        __syncthreads();
    }
    if (tid == 0) out[0] = sa[0] / sb[0];
}

// ---------------------------------------------------------------------------
extern "C" void kernel_launch(void* const* d_in, const int* in_sizes, int n_in,
                              void* d_out, int out_size)
{
    const float* x      = (const float*)d_in[0];
    const float* W1     = (const float*)d_in[1];
    const float* b1     = (const float*)d_in[2];
    const float* W2     = (const float*)d_in[3];
    const float* b2     = (const float*)d_in[4];
    const float* cw     = (const float*)d_in[5];
    const int*   esrc   = (const int*)d_in[6];
    const int*   edst   = (const int*)d_in[7];
    const int*   labels = (const int*)d_in[8];
    float* out = (float*)d_out;

    dim3 ggrid((NNODES + BM - 1) / BM, NOUT / BN);   // 391 x 4
    gemm_kernel<<<ggrid, 256>>>(x, W1);
    edge_kernel<<<EDGE_BLOCKS, 256>>>(b1, W2, b2, cw, esrc, edst, labels, out);
    finalize_kernel<<<1, 256>>>(out);
}

// round 3
// speedup vs baseline: 2.8431x; 2.8389x over previous
#include <cuda_runtime.h>
#include <math.h>

// Problem constants (fixed by the dataset)
#define NNODES 50000
#define HDIM   768
#define D1DIM  256
#define NOUT   512        // 2*D1: [A | B] per node
#define NEDGES 200000
#define NCLS   2

// GEMM tiling: 128x128 block, BK=16, tf32 mma.sync m16n8k8
#define BM 128
#define BN 128
#define BK 16
#define LDS 20            // padded smem row stride (floats); {20g+tg}%32 hits all banks

#define EDGE_WARPS 8
#define EDGE_BLOCKS (NEDGES / EDGE_WARPS)  // 25000

// Scratch (static device globals; no runtime allocation)
__device__ float g_AB[(size_t)NNODES * NOUT];        // ~102.4 MB
__device__ float g_partials[2 * EDGE_BLOCKS];

// ---------------------------------------------------------------------------
// helpers
// ---------------------------------------------------------------------------
__device__ __forceinline__ void cp_async16(float* smem, const float* gmem) {
    unsigned s = (unsigned)__cvta_generic_to_shared(smem);
    asm volatile("cp.async.cg.shared.global [%0], [%1], 16;" :: "r"(s), "l"(gmem));
}
#define CP_COMMIT  asm volatile("cp.async.commit_group;")
#define CP_WAIT1   asm volatile("cp.async.wait_group 1;")
#define CP_WAIT0   asm volatile("cp.async.wait_group 0;")

__device__ __forceinline__ unsigned f2tf32(float f) {
    unsigned u;
    asm("cvt.rna.tf32.f32 %0, %1;" : "=r"(u) : "f"(f));
    return u;
}

#define MMA_TF32(c, a, b)                                                     \
    asm volatile(                                                             \
        "mma.sync.aligned.m16n8k8.row.col.f32.tf32.tf32.f32 "                 \
        "{%0,%1,%2,%3},{%4,%5,%6,%7},{%8,%9},{%0,%1,%2,%3};"                  \
        : "+f"((c)[0]), "+f"((c)[1]), "+f"((c)[2]), "+f"((c)[3])              \
        : "r"((a)[0]), "r"((a)[1]), "r"((a)[2]), "r"((a)[3]),                 \
          "r"((b)[0]), "r"((b)[1]))

// ---------------------------------------------------------------------------
// Kernel 1: AB = x @ Wcat^T via tf32 tensor-core MMA.
//   A tile: x[m0:m0+128, kt:kt+16]    stored smem [m][k] stride 20
//   B tile: Wbase rows (output dims)  stored smem [n][k] stride 20
// 8 warps, warp tile 64x32, per warp 4x4 m16n8k8 tiles per k-step.
// ---------------------------------------------------------------------------
__global__ __launch_bounds__(256) void gemm_kernel(const float* __restrict__ x,
                                                   const float* __restrict__ W1)
{
    __shared__ __align__(16) float sA[2][BM * LDS];
    __shared__ __align__(16) float sB[2][BN * LDS];

    const int tid  = threadIdx.x;
    const int lane = tid & 31;
    const int g    = lane >> 2;        // 0..7
    const int tg   = lane & 3;         // 0..3
    const int warp = tid >> 5;
    const int wm   = (warp >> 2) * 64; // warp m offset within block
    const int wn   = (warp & 3) * 32;  // warp n offset within block

    const int m0 = blockIdx.x * BM;
    const int n0 = blockIdx.y * BN;

    // n-block never straddles the D1=256 boundary (BN=128)
    const float* Wbase = (n0 < D1DIM)
        ? (W1 + (size_t)n0 * (2 * HDIM))
        : (W1 + (size_t)(n0 - D1DIM) * (2 * HDIM) + HDIM);

    // per-thread load coords: 2 float4 per tile per thread
    float acc[4][4][4];
    #pragma unroll
    for (int i = 0; i < 4; i++)
        #pragma unroll
        for (int j = 0; j < 4; j++)
            #pragma unroll
            for (int v = 0; v < 4; v++) acc[i][j][v] = 0.f;

    // ---- prologue load ----
    {
        #pragma unroll
        for (int l = 0; l < 2; l++) {
            int idx = tid + l * 256;        // 0..511
            int row = idx >> 2;             // 0..127
            int c4  = idx & 3;              // float4 within 16 k
            int gm  = m0 + row; if (gm > NNODES - 1) gm = NNODES - 1;
            cp_async16(&sA[0][row * LDS + c4 * 4], x + (size_t)gm * HDIM + c4 * 4);
            cp_async16(&sB[0][row * LDS + c4 * 4], Wbase + (size_t)row * (2 * HDIM) + c4 * 4);
        }
        CP_COMMIT;
    }

    const int NIT = HDIM / BK;  // 48
    for (int it = 0; it < NIT; ++it) {
        const int s = it & 1;
        if (it + 1 < NIT) {
            const int kt = (it + 1) * BK;
            #pragma unroll
            for (int l = 0; l < 2; l++) {
                int idx = tid + l * 256;
                int row = idx >> 2;
                int c4  = idx & 3;
                int gm  = m0 + row; if (gm > NNODES - 1) gm = NNODES - 1;
                cp_async16(&sA[s ^ 1][row * LDS + c4 * 4], x + (size_t)gm * HDIM + kt + c4 * 4);
                cp_async16(&sB[s ^ 1][row * LDS + c4 * 4], Wbase + (size_t)row * (2 * HDIM) + kt + c4 * 4);
            }
            CP_COMMIT;
            CP_WAIT1;
        } else {
            CP_WAIT0;
        }
        __syncthreads();

        const float* As_ = sA[s];
        const float* Bs_ = sB[s];
        #pragma unroll
        for (int kk = 0; kk < 2; kk++) {      // two k=8 steps per BK=16
            unsigned af[4][4], bf[4][2];
            #pragma unroll
            for (int mi = 0; mi < 4; mi++) {
                const float* p = As_ + (wm + mi * 16 + g) * LDS + kk * 8 + tg;
                af[mi][0] = f2tf32(p[0]);
                af[mi][1] = f2tf32(p[8 * LDS]);
                af[mi][2] = f2tf32(p[4]);
                af[mi][3] = f2tf32(p[8 * LDS + 4]);
            }
            #pragma unroll
            for (int ni = 0; ni < 4; ni++) {
                const float* p = Bs_ + (wn + ni * 8 + g) * LDS + kk * 8 + tg;
                bf[ni][0] = f2tf32(p[0]);
                bf[ni][1] = f2tf32(p[4]);
            }
            #pragma unroll
            for (int mi = 0; mi < 4; mi++)
                #pragma unroll
                for (int ni = 0; ni < 4; ni++)
                    MMA_TF32(acc[mi][ni], af[mi], bf[ni]);
        }
        __syncthreads();
    }

    // ---- store: c0/c1 at (row, 2tg), c2/c3 at (row+8, 2tg) ----
    #pragma unroll
    for (int mi = 0; mi < 4; mi++) {
        #pragma unroll
        for (int ni = 0; ni < 4; ni++) {
            const int gm = m0 + wm + mi * 16 + g;
            const int gn = n0 + wn + ni * 8 + 2 * tg;
            if (gm < NNODES) {
                float2 v0 = make_float2(acc[mi][ni][0], acc[mi][ni][1]);
                *(float2*)(g_AB + (size_t)gm * NOUT + gn) = v0;
            }
            if (gm + 8 < NNODES) {
                float2 v1 = make_float2(acc[mi][ni][2], acc[mi][ni][3]);
                *(float2*)(g_AB + (size_t)(gm + 8) * NOUT + gn) = v1;
            }
        }
    }
}

// ---------------------------------------------------------------------------
// Kernel 2: per-edge MLP tail. One warp per edge.
// ---------------------------------------------------------------------------
__global__ __launch_bounds__(256) void edge_kernel(const float* __restrict__ b1,
                                                   const float* __restrict__ W2,
                                                   const float* __restrict__ b2,
                                                   const float* __restrict__ cw,
                                                   const int* __restrict__ esrc,
                                                   const int* __restrict__ edst,
                                                   const int* __restrict__ labels,
                                                   float* __restrict__ out)
{
    __shared__ float s_b1[D1DIM];
    __shared__ float s_W2[2 * D1DIM];
    __shared__ float s_wn[EDGE_WARPS];
    __shared__ float s_w[EDGE_WARPS];

    const int tid  = threadIdx.x;
    const int lane = tid & 31;
    const int warp = tid >> 5;

    if (tid < D1DIM) s_b1[tid] = b1[tid];
    s_W2[tid]       = W2[tid];
    s_W2[tid + 256] = W2[tid + 256];
    __syncthreads();

    const int edge = blockIdx.x * EDGE_WARPS + warp;

    float acc0 = 0.f, acc1 = 0.f;
    if (edge < NEDGES) {
        const int s = esrc[edge];
        const int d = edst[edge];
        const float* pa = g_AB + (size_t)s * NOUT;           // A half
        const float* pb = g_AB + (size_t)d * NOUT + D1DIM;   // B half
        #pragma unroll
        for (int i = 0; i < D1DIM / 32; i++) {
            const int j = lane + i * 32;
            float v = pa[j] + pb[j] + s_b1[j];
            float h = 0.5f * v * (1.0f + erff(v * 0.70710678118654752f));
            acc0 = fmaf(h, s_W2[j], acc0);
            acc1 = fmaf(h, s_W2[256 + j], acc1);
        }
    }
    #pragma unroll
    for (int o = 16; o > 0; o >>= 1) {
        acc0 += __shfl_xor_sync(0xFFFFFFFFu, acc0, o);
        acc1 += __shfl_xor_sync(0xFFFFFFFFu, acc1, o);
    }

    float wn = 0.f, wsum = 0.f;
    if (lane == 0 && edge < NEDGES) {
        const float l0 = acc0 + __ldg(&b2[0]);
        const float l1 = acc1 + __ldg(&b2[1]);
        const float m  = fmaxf(l0, l1);
        const float e0 = expf(l0 - m);
        const float e1 = expf(l1 - m);
        const float ssum = e0 + e1;
        const float inv  = 1.0f / ssum;
        out[1 + 2 * edge]     = e0 * inv;
        out[1 + 2 * edge + 1] = e1 * inv;
        const int lb  = labels[edge];
        const float ll   = lb ? l1 : l0;
        const float logp = (ll - m) - logf(ssum);
        const float w    = __ldg(&cw[lb]);
        wn   = -w * logp;
        wsum = w;
    }
    if (lane == 0) { s_wn[warp] = wn; s_w[warp] = wsum; }
    __syncthreads();
    if (tid == 0) {
        float a = 0.f, b = 0.f;
        #pragma unroll
        for (int i = 0; i < EDGE_WARPS; i++) { a += s_wn[i]; b += s_w[i]; }
        g_partials[blockIdx.x]               = a;
        g_partials[EDGE_BLOCKS + blockIdx.x] = b;
    }
}

// ---------------------------------------------------------------------------
// Kernel 3: deterministic final reduction -> loss at out[0]
// ---------------------------------------------------------------------------
__global__ __launch_bounds__(256) void finalize_kernel(float* __restrict__ out)
{
    __shared__ float sa[256];
    __shared__ float sb[256];
    const int tid = threadIdx.x;
    float a = 0.f, b = 0.f;
    for (int i = tid; i < EDGE_BLOCKS; i += 256) {
        a += g_partials[i];
        b += g_partials[EDGE_BLOCKS + i];
    }
    sa[tid] = a; sb[tid] = b;
    __syncthreads();
    for (int o = 128; o > 0; o >>= 1) {
        if (tid < o) { sa[tid] += sa[tid + o]; sb[tid] += sb[tid + o]; }
        __syncthreads();
    }
    if (tid == 0) out[0] = sa[0] / sb[0];
}

// ---------------------------------------------------------------------------
extern "C" void kernel_launch(void* const* d_in, const int* in_sizes, int n_in,
                              void* d_out, int out_size)
{
    const float* x      = (const float*)d_in[0];
    const float* W1     = (const float*)d_in[1];
    const float* b1     = (const float*)d_in[2];
    const float* W2     = (const float*)d_in[3];
    const float* b2     = (const float*)d_in[4];
    const float* cw     = (const float*)d_in[5];
    const int*   esrc   = (const int*)d_in[6];
    const int*   edst   = (const int*)d_in[7];
    const int*   labels = (const int*)d_in[8];
    float* out = (float*)d_out;

    dim3 ggrid((NNODES + BM - 1) / BM, NOUT / BN);   // 391 x 4
    gemm_kernel<<<ggrid, 256>>>(x, W1);
    edge_kernel<<<EDGE_BLOCKS, 256>>>(b1, W2, b2, cw, esrc, edst, labels, out);
    finalize_kernel<<<1, 256>>>(out);
}

// round 4
// speedup vs baseline: 2.9022x; 1.0208x over previous
#include <cuda_runtime.h>
#include <cuda_fp16.h>
#include <math.h>

// Problem constants (fixed by the dataset)
#define NNODES 50000
#define HDIM   768
#define D1DIM  256
#define NOUT   512        // 2*D1: [A | B] per node
#define NEDGES 200000
#define NCLS   2

// GEMM tiling: 128x128 block, BK=16, tf32 mma.sync m16n8k8
#define BM 128
#define BN 128
#define BK 16
#define LDS 20            // padded smem row stride; conflict-free for ldmatrix

#define EDGE_WARPS 8
#define EDGE_BLOCKS (NEDGES / EDGE_WARPS)  // 25000

// Scratch (static device globals; no runtime allocation)
__device__ __half g_AB[(size_t)NNODES * NOUT];       // ~51.2 MB -> fits in L2
__device__ float  g_partials[2 * EDGE_BLOCKS];

// ---------------------------------------------------------------------------
// helpers
// ---------------------------------------------------------------------------
__device__ __forceinline__ unsigned f2tf32(float f) {
    unsigned u;
    asm("cvt.rna.tf32.f32 %0, %1;" : "=r"(u) : "f"(f));
    return u;
}

__device__ __forceinline__ uint4 cvt4(float4 v) {
    uint4 r;
    r.x = f2tf32(v.x); r.y = f2tf32(v.y); r.z = f2tf32(v.z); r.w = f2tf32(v.w);
    return r;
}

__device__ __forceinline__ void ldsm_x4(unsigned& r0, unsigned& r1,
                                        unsigned& r2, unsigned& r3, unsigned addr) {
    asm volatile("ldmatrix.sync.aligned.m8n8.x4.shared.b16 {%0,%1,%2,%3}, [%4];"
                 : "=r"(r0), "=r"(r1), "=r"(r2), "=r"(r3) : "r"(addr));
}

#define MMA_TF32(c, a, b)                                                     \
    asm volatile(                                                             \
        "mma.sync.aligned.m16n8k8.row.col.f32.tf32.tf32.f32 "                 \
        "{%0,%1,%2,%3},{%4,%5,%6,%7},{%8,%9},{%0,%1,%2,%3};"                  \
        : "+f"((c)[0]), "+f"((c)[1]), "+f"((c)[2]), "+f"((c)[3])              \
        : "r"((a)[0]), "r"((a)[1]), "r"((a)[2]), "r"((a)[3]),                 \
          "r"((b)[0]), "r"((b)[1]))

// ---------------------------------------------------------------------------
// Kernel 1: AB = x @ Wcat^T via tf32 MMA.
// LDG (fp32) -> cvt.rna.tf32 -> STS pipeline: smem holds pre-converted tf32,
// fragments loaded with ldmatrix.x4 -> inner loop has NO cvt, few LDS issues.
// ---------------------------------------------------------------------------
__global__ __launch_bounds__(256) void gemm_kernel(const float* __restrict__ x,
                                                   const float* __restrict__ W1)
{
    __shared__ __align__(16) unsigned sA[2][BM * LDS];
    __shared__ __align__(16) unsigned sB[2][BN * LDS];

    const int tid  = threadIdx.x;
    const int lane = tid & 31;
    const int warp = tid >> 5;
    const int wm   = (warp >> 2) * 64;     // warp m offset in block
    const int wn   = (warp & 3) * 32;      // warp n offset in block

    const int m0 = blockIdx.x * BM;
    const int n0 = blockIdx.y * BN;

    // n-block never straddles the D1=256 boundary (BN=128)
    const float* Wbase = (n0 < D1DIM)
        ? (W1 + (size_t)n0 * (2 * HDIM))
        : (W1 + (size_t)(n0 - D1DIM) * (2 * HDIM) + HDIM);

    // ---- per-thread global load coords (2 float4 per tile) ----
    const int row0 = tid >> 2;             // 0..63
    const int c4   = tid & 3;
    const int row1 = row0 + 64;            // 64..127
    int gm0 = m0 + row0; if (gm0 > NNODES - 1) gm0 = NNODES - 1;
    int gm1 = m0 + row1; if (gm1 > NNODES - 1) gm1 = NNODES - 1;
    const float* pAx0 = x + (size_t)gm0 * HDIM + c4 * 4;
    const float* pAx1 = x + (size_t)gm1 * HDIM + c4 * 4;
    const float* pBw0 = Wbase + (size_t)row0 * (2 * HDIM) + c4 * 4;
    const float* pBw1 = Wbase + (size_t)row1 * (2 * HDIM) + c4 * 4;

    const unsigned baseA0 = (unsigned)__cvta_generic_to_shared(&sA[0][0]);
    const unsigned baseA1 = (unsigned)__cvta_generic_to_shared(&sA[1][0]);
    const unsigned baseB0 = (unsigned)__cvta_generic_to_shared(&sB[0][0]);
    const unsigned baseB1 = (unsigned)__cvta_generic_to_shared(&sB[1][0]);

    // ldmatrix per-lane row/k offsets (element units)
    const int aRow = wm + (lane & 15);                         // + mi*16
    const int aK   = (lane >> 4) * 4;                          // 0 or 4
    const int bRow = wn + ((lane >> 4) & 1) * 8 + (lane & 7);  // + p*16
    const int bK   = ((lane >> 3) & 1) * 4;                    // 0 or 4

    float acc[4][4][4];
    #pragma unroll
    for (int i = 0; i < 4; i++)
        #pragma unroll
        for (int j = 0; j < 4; j++)
            #pragma unroll
            for (int v = 0; v < 4; v++) acc[i][j][v] = 0.f;

    // ---- prefetch iter 0 into registers ----
    float4 ra0 = *(const float4*)(pAx0);
    float4 ra1 = *(const float4*)(pAx1);
    float4 rb0 = *(const float4*)(pBw0);
    float4 rb1 = *(const float4*)(pBw1);

    const int NIT = HDIM / BK;  // 48
    for (int it = 0; it < NIT; ++it) {
        const int s = it & 1;
        const unsigned bA = s ? baseA1 : baseA0;
        const unsigned bB = s ? baseB1 : baseB0;

        // ---- convert + store current tile to smem (tf32 bit patterns) ----
        *(uint4*)&sA[s][row0 * LDS + c4 * 4] = cvt4(ra0);
        *(uint4*)&sA[s][row1 * LDS + c4 * 4] = cvt4(ra1);
        *(uint4*)&sB[s][row0 * LDS + c4 * 4] = cvt4(rb0);
        *(uint4*)&sB[s][row1 * LDS + c4 * 4] = cvt4(rb1);
        __syncthreads();

        // ---- prefetch next tile (overlaps with MMA below) ----
        if (it + 1 < NIT) {
            const int kt = (it + 1) * BK;
            ra0 = *(const float4*)(pAx0 + kt);
            ra1 = *(const float4*)(pAx1 + kt);
            rb0 = *(const float4*)(pBw0 + kt);
            rb1 = *(const float4*)(pBw1 + kt);
        }

        // ---- compute: 2 k=8 steps, ldmatrix fragment loads ----
        #pragma unroll
        for (int kk = 0; kk < 2; kk++) {
            unsigned af[4][4], bf[4][2];
            #pragma unroll
            for (int mi = 0; mi < 4; mi++) {
                unsigned addr = bA + (unsigned)((aRow + mi * 16) * LDS + kk * 8 + aK) * 4u;
                ldsm_x4(af[mi][0], af[mi][1], af[mi][2], af[mi][3], addr);
            }
            #pragma unroll
            for (int p = 0; p < 2; p++) {
                unsigned addr = bB + (unsigned)((bRow + p * 16) * LDS + kk * 8 + bK) * 4u;
                ldsm_x4(bf[2 * p][0], bf[2 * p][1], bf[2 * p + 1][0], bf[2 * p + 1][1], addr);
            }
            #pragma unroll
            for (int mi = 0; mi < 4; mi++)
                #pragma unroll
                for (int ni = 0; ni < 4; ni++)
                    MMA_TF32(acc[mi][ni], af[mi], bf[ni]);
        }
        // one barrier per iter suffices with double buffering: the next
        // write to this buffer is 2 iters away, ordered by the next barrier.
        __syncthreads();
    }

    // ---- store to fp16 AB ----
    const int g  = lane >> 2;
    const int tg = lane & 3;
    #pragma unroll
    for (int mi = 0; mi < 4; mi++) {
        #pragma unroll
        for (int ni = 0; ni < 4; ni++) {
            const int gm = m0 + wm + mi * 16 + g;
            const int gn = n0 + wn + ni * 8 + 2 * tg;
            if (gm < NNODES) {
                *(__half2*)(g_AB + (size_t)gm * NOUT + gn) =
                    __floats2half2_rn(acc[mi][ni][0], acc[mi][ni][1]);
            }
            if (gm + 8 < NNODES) {
                *(__half2*)(g_AB + (size_t)(gm + 8) * NOUT + gn) =
                    __floats2half2_rn(acc[mi][ni][2], acc[mi][ni][3]);
            }
        }
    }
}

// ---------------------------------------------------------------------------
// Kernel 2: per-edge MLP tail. One warp per edge; 16B vector gathers of fp16 AB.
// ---------------------------------------------------------------------------
__global__ __launch_bounds__(256) void edge_kernel(const float* __restrict__ b1,
                                                   const float* __restrict__ W2,
                                                   const float* __restrict__ b2,
                                                   const float* __restrict__ cw,
                                                   const int* __restrict__ esrc,
                                                   const int* __restrict__ edst,
                                                   const int* __restrict__ labels,
                                                   float* __restrict__ out)
{
    __shared__ float s_b1[D1DIM];
    __shared__ float s_W2[2 * D1DIM];
    __shared__ float s_wn[EDGE_WARPS];
    __shared__ float s_w[EDGE_WARPS];

    const int tid  = threadIdx.x;
    const int lane = tid & 31;
    const int warp = tid >> 5;

    if (tid < D1DIM) s_b1[tid] = b1[tid];
    s_W2[tid]       = W2[tid];
    s_W2[tid + 256] = W2[tid + 256];
    __syncthreads();

    const int edge = blockIdx.x * EDGE_WARPS + warp;

    float acc0 = 0.f, acc1 = 0.f;
    if (edge < NEDGES) {
        const int s = esrc[edge];
        const int d = edst[edge];
        const int j0 = lane * 8;      // 8 consecutive hidden dims per lane
        const uint4 va = *(const uint4*)(g_AB + (size_t)s * NOUT + j0);
        const uint4 vb = *(const uint4*)(g_AB + (size_t)d * NOUT + D1DIM + j0);
        const __half2* ha = (const __half2*)&va;
        const __half2* hb = (const __half2*)&vb;
        #pragma unroll
        for (int t = 0; t < 4; t++) {
            const float2 fa = __half22float2(ha[t]);
            const float2 fb = __half22float2(hb[t]);
            const int j = j0 + 2 * t;
            float v0 = fa.x + fb.x + s_b1[j];
            float h0 = 0.5f * v0 * (1.0f + erff(v0 * 0.70710678118654752f));
            acc0 = fmaf(h0, s_W2[j], acc0);
            acc1 = fmaf(h0, s_W2[256 + j], acc1);
            float v1 = fa.y + fb.y + s_b1[j + 1];
            float h1 = 0.5f * v1 * (1.0f + erff(v1 * 0.70710678118654752f));
            acc0 = fmaf(h1, s_W2[j + 1], acc0);
            acc1 = fmaf(h1, s_W2[256 + j + 1], acc1);
        }
    }
    #pragma unroll
    for (int o = 16; o > 0; o >>= 1) {
        acc0 += __shfl_xor_sync(0xFFFFFFFFu, acc0, o);
        acc1 += __shfl_xor_sync(0xFFFFFFFFu, acc1, o);
    }

    float wn = 0.f, wsum = 0.f;
    if (lane == 0 && edge < NEDGES) {
        const float l0 = acc0 + __ldg(&b2[0]);
        const float l1 = acc1 + __ldg(&b2[1]);
        const float m  = fmaxf(l0, l1);
        const float e0 = expf(l0 - m);
        const float e1 = expf(l1 - m);
        const float ssum = e0 + e1;
        const float inv  = 1.0f / ssum;
        out[1 + 2 * edge]     = e0 * inv;
        out[1 + 2 * edge + 1] = e1 * inv;
        const int lb  = labels[edge];
        const float ll   = lb ? l1 : l0;
        const float logp = (ll - m) - logf(ssum);
        const float w    = __ldg(&cw[lb]);
        wn   = -w * logp;
        wsum = w;
    }
    if (lane == 0) { s_wn[warp] = wn; s_w[warp] = wsum; }
    __syncthreads();
    if (tid == 0) {
        float a = 0.f, b = 0.f;
        #pragma unroll
        for (int i = 0; i < EDGE_WARPS; i++) { a += s_wn[i]; b += s_w[i]; }
        g_partials[blockIdx.x]               = a;
        g_partials[EDGE_BLOCKS + blockIdx.x] = b;
    }
}

// ---------------------------------------------------------------------------
// Kernel 3: deterministic final reduction -> loss at out[0]
// ---------------------------------------------------------------------------
__global__ __launch_bounds__(256) void finalize_kernel(float* __restrict__ out)
{
    __shared__ float sa[256];
    __shared__ float sb[256];
    const int tid = threadIdx.x;
    float a = 0.f, b = 0.f;
    for (int i = tid; i < EDGE_BLOCKS; i += 256) {
        a += g_partials[i];
        b += g_partials[EDGE_BLOCKS + i];
    }
    sa[tid] = a; sb[tid] = b;
    __syncthreads();
    for (int o = 128; o > 0; o >>= 1) {
        if (tid < o) { sa[tid] += sa[tid + o]; sb[tid] += sb[tid + o]; }
        __syncthreads();
    }
    if (tid == 0) out[0] = sa[0] / sb[0];
}

// ---------------------------------------------------------------------------
extern "C" void kernel_launch(void* const* d_in, const int* in_sizes, int n_in,
                              void* d_out, int out_size)
{
    const float* x      = (const float*)d_in[0];
    const float* W1     = (const float*)d_in[1];
    const float* b1     = (const float*)d_in[2];
    const float* W2     = (const float*)d_in[3];
    const float* b2     = (const float*)d_in[4];
    const float* cw     = (const float*)d_in[5];
    const int*   esrc   = (const int*)d_in[6];
    const int*   edst   = (const int*)d_in[7];
    const int*   labels = (const int*)d_in[8];
    float* out = (float*)d_out;

    dim3 ggrid((NNODES + BM - 1) / BM, NOUT / BN);   // 391 x 4
    gemm_kernel<<<ggrid, 256>>>(x, W1);
    edge_kernel<<<EDGE_BLOCKS, 256>>>(b1, W2, b2, cw, esrc, edst, labels, out);
    finalize_kernel<<<1, 256>>>(out);
}

// round 5
// speedup vs baseline: 2.9173x; 1.0052x over previous
#include <cuda_runtime.h>
#include <cuda_fp16.h>
#include <math.h>

// Problem constants (fixed by the dataset)
#define NNODES 50000
#define HDIM   768
#define D1DIM  256
#define NOUT   512        // 2*D1: [A | B] per node
#define NEDGES 200000
#define NCLS   2

// GEMM tiling: 128x128 block, BK=16, tf32 mma.sync m16n8k8, 3-stage cp.async
#define BM 128
#define BN 128
#define BK 16
#define LDS 20            // padded smem row stride; conflict-free for ldmatrix
#define NSTAGE 3

#define EDGE_WARPS 8
#define EDGES_PER_WARP 2
#define EDGES_PER_BLOCK (EDGE_WARPS * EDGES_PER_WARP)     // 16
#define EDGE_BLOCKS (NEDGES / EDGES_PER_BLOCK)            // 12500

// Scratch (static device globals; no runtime allocation)
__device__ __half g_AB[(size_t)NNODES * NOUT];       // ~51.2 MB -> L2-resident
__device__ float  g_partials[2 * EDGE_BLOCKS];

// ---------------------------------------------------------------------------
// helpers
// ---------------------------------------------------------------------------
__device__ __forceinline__ void cp_async16(float* smem, const float* gmem) {
    unsigned s = (unsigned)__cvta_generic_to_shared(smem);
    asm volatile("cp.async.cg.shared.global [%0], [%1], 16;" :: "r"(s), "l"(gmem));
}
#define CP_COMMIT  asm volatile("cp.async.commit_group;")
#define CP_WAIT1   asm volatile("cp.async.wait_group 1;")
#define CP_WAIT0   asm volatile("cp.async.wait_group 0;")

__device__ __forceinline__ unsigned f2tf32(float f) {
    unsigned u;
    asm("cvt.rna.tf32.f32 %0, %1;" : "=r"(u) : "f"(f));
    return u;
}
__device__ __forceinline__ unsigned u2tf32(unsigned x) {
    return f2tf32(__uint_as_float(x));
}

__device__ __forceinline__ void ldsm_x4(unsigned& r0, unsigned& r1,
                                        unsigned& r2, unsigned& r3, unsigned addr) {
    asm volatile("ldmatrix.sync.aligned.m8n8.x4.shared.b16 {%0,%1,%2,%3}, [%4];"
                 : "=r"(r0), "=r"(r1), "=r"(r2), "=r"(r3) : "r"(addr));
}

#define MMA_TF32(c, a, b)                                                     \
    asm volatile(                                                             \
        "mma.sync.aligned.m16n8k8.row.col.f32.tf32.tf32.f32 "                 \
        "{%0,%1,%2,%3},{%4,%5,%6,%7},{%8,%9},{%0,%1,%2,%3};"                  \
        : "+f"((c)[0]), "+f"((c)[1]), "+f"((c)[2]), "+f"((c)[3])              \
        : "r"((a)[0]), "r"((a)[1]), "r"((a)[2]), "r"((a)[3]),                 \
          "r"((b)[0]), "r"((b)[1]))

// ---------------------------------------------------------------------------
// Kernel 1: AB = x @ Wcat^T via tf32 MMA.
// 3-stage cp.async pipeline; ldmatrix.x4 fragment loads; cvt.rna.tf32 applied
// to fragments post-ldmatrix (no blocking LDG, minimal issue slots).
// ---------------------------------------------------------------------------
__global__ __launch_bounds__(256) void gemm_kernel(const float* __restrict__ x,
                                                   const float* __restrict__ W1)
{
    __shared__ __align__(16) float sA[NSTAGE][BM * LDS];
    __shared__ __align__(16) float sB[NSTAGE][BN * LDS];

    const int tid  = threadIdx.x;
    const int lane = tid & 31;
    const int warp = tid >> 5;
    const int wm   = (warp >> 2) * 64;     // warp m offset in block
    const int wn   = (warp & 3) * 32;      // warp n offset in block

    const int m0 = blockIdx.x * BM;
    const int n0 = blockIdx.y * BN;

    // n-block never straddles the D1=256 boundary (BN=128)
    const float* Wbase = (n0 < D1DIM)
        ? (W1 + (size_t)n0 * (2 * HDIM))
        : (W1 + (size_t)(n0 - D1DIM) * (2 * HDIM) + HDIM);

    // ---- per-thread async-load coords (2 float4 per A/B tile) ----
    const int row0 = tid >> 2;             // 0..63
    const int c4   = tid & 3;
    const int row1 = row0 + 64;            // 64..127
    int gm0 = m0 + row0; if (gm0 > NNODES - 1) gm0 = NNODES - 1;
    int gm1 = m0 + row1; if (gm1 > NNODES - 1) gm1 = NNODES - 1;
    const float* pAx0 = x + (size_t)gm0 * HDIM + c4 * 4;
    const float* pAx1 = x + (size_t)gm1 * HDIM + c4 * 4;
    const float* pBw0 = Wbase + (size_t)row0 * (2 * HDIM) + c4 * 4;
    const float* pBw1 = Wbase + (size_t)row1 * (2 * HDIM) + c4 * 4;

    // ldmatrix per-lane row/k offsets (element units)
    const int aRow = wm + (lane & 15);                         // + mi*16
    const int aK   = (lane >> 4) * 4;                          // 0 or 4
    const int bRow = wn + ((lane >> 4) & 1) * 8 + (lane & 7);  // + p*16
    const int bK   = ((lane >> 3) & 1) * 4;                    // 0 or 4

    unsigned smA[NSTAGE], smB[NSTAGE];
    #pragma unroll
    for (int st = 0; st < NSTAGE; st++) {
        smA[st] = (unsigned)__cvta_generic_to_shared(&sA[st][0]);
        smB[st] = (unsigned)__cvta_generic_to_shared(&sB[st][0]);
    }

    float acc[4][4][4];
    #pragma unroll
    for (int i = 0; i < 4; i++)
        #pragma unroll
        for (int j = 0; j < 4; j++)
            #pragma unroll
            for (int v = 0; v < 4; v++) acc[i][j][v] = 0.f;

    // ---- prologue: prefetch stages 0 and 1 ----
    #pragma unroll
    for (int st = 0; st < 2; st++) {
        const int kt = st * BK;
        cp_async16(&sA[st][row0 * LDS + c4 * 4], pAx0 + kt);
        cp_async16(&sA[st][row1 * LDS + c4 * 4], pAx1 + kt);
        cp_async16(&sB[st][row0 * LDS + c4 * 4], pBw0 + kt);
        cp_async16(&sB[st][row1 * LDS + c4 * 4], pBw1 + kt);
        CP_COMMIT;
    }

    const int NIT = HDIM / BK;  // 48
    int s = 0;                  // stage of current iter
    for (int it = 0; it < NIT; ++it) {
        if (it < NIT - 1) { CP_WAIT1; } else { CP_WAIT0; }
        __syncthreads();   // stage s data visible to all; stage (it+2)%3 free

        // ---- prefetch stage it+2 (its buffer was computed at iter it-1) ----
        if (it + 2 < NIT) {
            const int st = (it + 2) % NSTAGE;
            const int kt = (it + 2) * BK;
            cp_async16(&sA[st][row0 * LDS + c4 * 4], pAx0 + kt);
            cp_async16(&sA[st][row1 * LDS + c4 * 4], pAx1 + kt);
            cp_async16(&sB[st][row0 * LDS + c4 * 4], pBw0 + kt);
            cp_async16(&sB[st][row1 * LDS + c4 * 4], pBw1 + kt);
            CP_COMMIT;
        }

        const unsigned bA = smA[s];
        const unsigned bB = smB[s];
        // ---- compute: 2 k=8 steps; ldmatrix then cvt fragments ----
        #pragma unroll
        for (int kk = 0; kk < 2; kk++) {
            unsigned af[4][4], bf[4][2];
            #pragma unroll
            for (int mi = 0; mi < 4; mi++) {
                unsigned addr = bA + (unsigned)((aRow + mi * 16) * LDS + kk * 8 + aK) * 4u;
                ldsm_x4(af[mi][0], af[mi][1], af[mi][2], af[mi][3], addr);
            }
            #pragma unroll
            for (int p = 0; p < 2; p++) {
                unsigned addr = bB + (unsigned)((bRow + p * 16) * LDS + kk * 8 + bK) * 4u;
                ldsm_x4(bf[2 * p][0], bf[2 * p][1], bf[2 * p + 1][0], bf[2 * p + 1][1], addr);
            }
            #pragma unroll
            for (int mi = 0; mi < 4; mi++)
                #pragma unroll
                for (int v = 0; v < 4; v++) af[mi][v] = u2tf32(af[mi][v]);
            #pragma unroll
            for (int ni = 0; ni < 4; ni++) {
                bf[ni][0] = u2tf32(bf[ni][0]);
                bf[ni][1] = u2tf32(bf[ni][1]);
            }
            #pragma unroll
            for (int mi = 0; mi < 4; mi++)
                #pragma unroll
                for (int ni = 0; ni < 4; ni++)
                    MMA_TF32(acc[mi][ni], af[mi], bf[ni]);
        }
        s = (s + 1 == NSTAGE) ? 0 : s + 1;
    }

    // ---- store to fp16 AB ----
    const int g  = lane >> 2;
    const int tg = lane & 3;
    #pragma unroll
    for (int mi = 0; mi < 4; mi++) {
        #pragma unroll
        for (int ni = 0; ni < 4; ni++) {
            const int gm = m0 + wm + mi * 16 + g;
            const int gn = n0 + wn + ni * 8 + 2 * tg;
            if (gm < NNODES) {
                *(__half2*)(g_AB + (size_t)gm * NOUT + gn) =
                    __floats2half2_rn(acc[mi][ni][0], acc[mi][ni][1]);
            }
            if (gm + 8 < NNODES) {
                *(__half2*)(g_AB + (size_t)(gm + 8) * NOUT + gn) =
                    __floats2half2_rn(acc[mi][ni][2], acc[mi][ni][3]);
            }
        }
    }
}

// ---------------------------------------------------------------------------
// Kernel 2: per-edge MLP tail. 2 edges per warp; all 4 gathers in flight
// before compute (MLP=4) to cover L2 latency.
// ---------------------------------------------------------------------------
__global__ __launch_bounds__(256) void edge_kernel(const float* __restrict__ b1,
                                                   const float* __restrict__ W2,
                                                   const float* __restrict__ b2,
                                                   const float* __restrict__ cw,
                                                   const int* __restrict__ esrc,
                                                   const int* __restrict__ edst,
                                                   const int* __restrict__ labels,
                                                   float* __restrict__ out)
{
    __shared__ float s_b1[D1DIM];
    __shared__ float s_W2[2 * D1DIM];
    __shared__ float s_wn[EDGE_WARPS];
    __shared__ float s_w[EDGE_WARPS];

    const int tid  = threadIdx.x;
    const int lane = tid & 31;
    const int warp = tid >> 5;

    if (tid < D1DIM) s_b1[tid] = b1[tid];
    s_W2[tid]       = W2[tid];
    s_W2[tid + 256] = W2[tid + 256];
    __syncthreads();

    const int e0 = blockIdx.x * EDGES_PER_BLOCK + warp * EDGES_PER_WARP;
    const int e1 = e0 + 1;

    const int j0 = lane * 8;      // 8 consecutive hidden dims per lane

    // issue all 4 gathers before any compute
    const int s0 = esrc[e0], d0 = edst[e0];
    const int s1 = esrc[e1], d1 = edst[e1];
    const uint4 va0 = *(const uint4*)(g_AB + (size_t)s0 * NOUT + j0);
    const uint4 vb0 = *(const uint4*)(g_AB + (size_t)d0 * NOUT + D1DIM + j0);
    const uint4 va1 = *(const uint4*)(g_AB + (size_t)s1 * NOUT + j0);
    const uint4 vb1 = *(const uint4*)(g_AB + (size_t)d1 * NOUT + D1DIM + j0);

    float a00 = 0.f, a01 = 0.f, a10 = 0.f, a11 = 0.f;
    {
        const __half2* ha0 = (const __half2*)&va0;
        const __half2* hb0 = (const __half2*)&vb0;
        const __half2* ha1 = (const __half2*)&va1;
        const __half2* hb1 = (const __half2*)&vb1;
        #pragma unroll
        for (int t = 0; t < 4; t++) {
            const int j = j0 + 2 * t;
            const float w0a = s_W2[j],     w0b = s_W2[j + 1];
            const float w1a = s_W2[256 + j], w1b = s_W2[256 + j + 1];
            const float bja = s_b1[j], bjb = s_b1[j + 1];
            {
                const float2 fa = __half22float2(ha0[t]);
                const float2 fb = __half22float2(hb0[t]);
                float v0 = fa.x + fb.x + bja;
                float h0 = 0.5f * v0 * (1.0f + erff(v0 * 0.70710678118654752f));
                a00 = fmaf(h0, w0a, a00); a01 = fmaf(h0, w1a, a01);
                float v1 = fa.y + fb.y + bjb;
                float h1 = 0.5f * v1 * (1.0f + erff(v1 * 0.70710678118654752f));
                a00 = fmaf(h1, w0b, a00); a01 = fmaf(h1, w1b, a01);
            }
            {
                const float2 fa = __half22float2(ha1[t]);
                const float2 fb = __half22float2(hb1[t]);
                float v0 = fa.x + fb.x + bja;
                float h0 = 0.5f * v0 * (1.0f + erff(v0 * 0.70710678118654752f));
                a10 = fmaf(h0, w0a, a10); a11 = fmaf(h0, w1a, a11);
                float v1 = fa.y + fb.y + bjb;
                float h1 = 0.5f * v1 * (1.0f + erff(v1 * 0.70710678118654752f));
                a10 = fmaf(h1, w0b, a10); a11 = fmaf(h1, w1b, a11);
            }
        }
    }
    #pragma unroll
    for (int o = 16; o > 0; o >>= 1) {
        a00 += __shfl_xor_sync(0xFFFFFFFFu, a00, o);
        a01 += __shfl_xor_sync(0xFFFFFFFFu, a01, o);
        a10 += __shfl_xor_sync(0xFFFFFFFFu, a10, o);
        a11 += __shfl_xor_sync(0xFFFFFFFFu, a11, o);
    }

    float wn = 0.f, wsum = 0.f;
    if (lane == 0) {
        const float bb0 = __ldg(&b2[0]);
        const float bb1 = __ldg(&b2[1]);
        // edge e0
        {
            const float l0 = a00 + bb0, l1 = a01 + bb1;
            const float m  = fmaxf(l0, l1);
            const float x0 = expf(l0 - m), x1 = expf(l1 - m);
            const float ssum = x0 + x1, inv = 1.0f / ssum;
            out[1 + 2 * e0]     = x0 * inv;
            out[1 + 2 * e0 + 1] = x1 * inv;
            const int lb = labels[e0];
            const float logp = ((lb ? l1 : l0) - m) - logf(ssum);
            const float w = __ldg(&cw[lb]);
            wn += -w * logp; wsum += w;
        }
        // edge e1
        {
            const float l0 = a10 + bb0, l1 = a11 + bb1;
            const float m  = fmaxf(l0, l1);
            const float x0 = expf(l0 - m), x1 = expf(l1 - m);
            const float ssum = x0 + x1, inv = 1.0f / ssum;
            out[1 + 2 * e1]     = x0 * inv;
            out[1 + 2 * e1 + 1] = x1 * inv;
            const int lb = labels[e1];
            const float logp = ((lb ? l1 : l0) - m) - logf(ssum);
            const float w = __ldg(&cw[lb]);
            wn += -w * logp; wsum += w;
        }
        s_wn[warp] = wn; s_w[warp] = wsum;
    }
    __syncthreads();
    if (tid == 0) {
        float a = 0.f, b = 0.f;
        #pragma unroll
        for (int i = 0; i < EDGE_WARPS; i++) { a += s_wn[i]; b += s_w[i]; }
        g_partials[blockIdx.x]               = a;
        g_partials[EDGE_BLOCKS + blockIdx.x] = b;
    }
}

// ---------------------------------------------------------------------------
// Kernel 3: deterministic final reduction -> loss at out[0]
// ---------------------------------------------------------------------------
__global__ __launch_bounds__(256) void finalize_kernel(float* __restrict__ out)
{
    __shared__ float sa[256];
    __shared__ float sb[256];
    const int tid = threadIdx.x;
    float a = 0.f, b = 0.f;
    for (int i = tid; i < EDGE_BLOCKS; i += 256) {
        a += g_partials[i];
        b += g_partials[EDGE_BLOCKS + i];
    }
    sa[tid] = a; sb[tid] = b;
    __syncthreads();
    for (int o = 128; o > 0; o >>= 1) {
        if (tid < o) { sa[tid] += sa[tid + o]; sb[tid] += sb[tid + o]; }
        __syncthreads();
    }
    if (tid == 0) out[0] = sa[0] / sb[0];
}

// ---------------------------------------------------------------------------
extern "C" void kernel_launch(void* const* d_in, const int* in_sizes, int n_in,
                              void* d_out, int out_size)
{
    const float* x      = (const float*)d_in[0];
    const float* W1     = (const float*)d_in[1];
    const float* b1     = (const float*)d_in[2];
    const float* W2     = (const float*)d_in[3];
    const float* b2     = (const float*)d_in[4];
    const float* cw     = (const float*)d_in[5];
    const int*   esrc   = (const int*)d_in[6];
    const int*   edst   = (const int*)d_in[7];
    const int*   labels = (const int*)d_in[8];
    float* out = (float*)d_out;

    dim3 ggrid((NNODES + BM - 1) / BM, NOUT / BN);   // 391 x 4
    gemm_kernel<<<ggrid, 256>>>(x, W1);
    edge_kernel<<<EDGE_BLOCKS, 256>>>(b1, W2, b2, cw, esrc, edst, labels, out);
    finalize_kernel<<<1, 256>>>(out);
}

// round 7
// speedup vs baseline: 4.0492x; 1.3880x over previous
#include <cuda_runtime.h>
#include <cuda_fp16.h>
#include <math.h>
#include <stdint.h>

// Problem constants (fixed by the dataset)
#define NNODES 50000
#define HDIM   768
#define D1DIM  256
#define NOUT   512        // 2*D1: [A | B] per node
#define NEDGES 200000

// GEMM tiling: 128x128 block, BK=32, fp16 mma.sync m16n8k16, 3-stage cp.async
#define BM 128
#define BN 128
#define BK 32
#define LDH 40            // smem row stride in halves (80B); conflict-free ldmatrix
#define NSTAGE 3
#define STAGE_H (BM * LDH)            // halves per tile stage (5120)

#define EDGE_WARPS 8
#define EDGES_PER_WARP 2
#define EDGES_PER_BLOCK (EDGE_WARPS * EDGES_PER_WARP)     // 16
#define EDGE_BLOCKS (NEDGES / EDGES_PER_BLOCK)            // 12500

// Scratch (static device globals; no runtime allocation)
__device__ __half g_xh[(size_t)NNODES * HDIM];       // x in fp16 (~77 MB)
__device__ __half g_Wh[(size_t)NOUT * HDIM];         // Wcat rows in fp16 (768 KB)
__device__ __half g_AB[(size_t)NNODES * NOUT];       // ~51 MB -> L2-resident
__device__ float  g_partials[2 * EDGE_BLOCKS];

// ---------------------------------------------------------------------------
// helpers
// ---------------------------------------------------------------------------
__device__ __forceinline__ void cp_async16(void* smem, const void* gmem) {
    unsigned s = (unsigned)__cvta_generic_to_shared(smem);
    asm volatile("cp.async.cg.shared.global [%0], [%1], 16;" :: "r"(s), "l"(gmem));
}
#define CP_COMMIT  asm volatile("cp.async.commit_group;")
#define CP_WAIT1   asm volatile("cp.async.wait_group 1;")
#define CP_WAIT0   asm volatile("cp.async.wait_group 0;")

__device__ __forceinline__ void ldsm_x4(unsigned& r0, unsigned& r1,
                                        unsigned& r2, unsigned& r3, unsigned addr) {
    asm volatile("ldmatrix.sync.aligned.m8n8.x4.shared.b16 {%0,%1,%2,%3}, [%4];"
                 : "=r"(r0), "=r"(r1), "=r"(r2), "=r"(r3) : "r"(addr));
}

#define MMA_F16(c, a, b)                                                      \
    asm volatile(                                                             \
        "mma.sync.aligned.m16n8k16.row.col.f32.f16.f16.f32 "                  \
        "{%0,%1,%2,%3},{%4,%5,%6,%7},{%8,%9},{%0,%1,%2,%3};"                  \
        : "+f"((c)[0]), "+f"((c)[1]), "+f"((c)[2]), "+f"((c)[3])              \
        : "r"((a)[0]), "r"((a)[1]), "r"((a)[2]), "r"((a)[3]),                 \
          "r"((b)[0]), "r"((b)[1]))

// ---------------------------------------------------------------------------
// Conversion pre-passes: fp32 -> fp16 globals
// ---------------------------------------------------------------------------
__global__ __launch_bounds__(256) void conv_x_kernel(const float* __restrict__ x)
{
    const size_t i = (size_t)blockIdx.x * 256 + threadIdx.x;   // float4 index
    const size_t n4 = (size_t)NNODES * HDIM / 4;
    if (i < n4) {
        float4 v = *(const float4*)(x + i * 4);
        __half2 h0 = __floats2half2_rn(v.x, v.y);
        __half2 h1 = __floats2half2_rn(v.z, v.w);
        uint2 o; o.x = *(uint32_t*)&h0; o.y = *(uint32_t*)&h1;
        *(uint2*)(g_xh + i * 4) = o;
    }
}

__global__ __launch_bounds__(256) void conv_w_kernel(const float* __restrict__ W1)
{
    const int i = blockIdx.x * 256 + threadIdx.x;   // float4 index
    const int n4 = NOUT * HDIM / 4;
    if (i < n4) {
        const int e = i * 4;
        const int n = e / HDIM;
        const int k = e % HDIM;
        const float* src = (n < D1DIM)
            ? (W1 + (size_t)n * (2 * HDIM) + k)
            : (W1 + (size_t)(n - D1DIM) * (2 * HDIM) + HDIM + k);
        float4 v = *(const float4*)src;
        __half2 h0 = __floats2half2_rn(v.x, v.y);
        __half2 h1 = __floats2half2_rn(v.z, v.w);
        uint2 o; o.x = *(uint32_t*)&h0; o.y = *(uint32_t*)&h1;
        *(uint2*)(g_Wh + e) = o;
    }
}

// ---------------------------------------------------------------------------
// Kernel 1: AB = x_h @ W_h^T via fp16 mma.sync m16n8k16 (fp32 accumulate).
// 3-stage cp.async pipeline, ldmatrix.x4 b16 fragment loads, no cvt anywhere.
// 8 warps, warp tile 64x32; per BK=32 iter: 12 LDSM + 32 MMA per warp.
// ---------------------------------------------------------------------------
__global__ __launch_bounds__(256) void gemm_kernel()
{
    extern __shared__ __align__(16) __half smem[];
    // layout: A stages [0,3*STAGE_H), B stages [3*STAGE_H, 6*STAGE_H)
    __half* sA = smem;
    __half* sB = smem + NSTAGE * STAGE_H;

    const int tid  = threadIdx.x;
    const int lane = tid & 31;
    const int warp = tid >> 5;
    const int wm   = (warp >> 2) * 64;     // warp m offset in block
    const int wn   = (warp & 3) * 32;      // warp n offset in block

    const int m0 = blockIdx.x * BM;
    const int n0 = blockIdx.y * BN;

    // ---- per-thread async-load coords: 2 chunks (16B = 8 halves) per tile ----
    // tile = 128 rows x 32 halves = 4 chunks/row = 512 chunks; 2 per thread
    const int row0 = tid >> 2;             // 0..63
    const int c4   = tid & 3;              // chunk within row
    const int row1 = row0 + 64;            // 64..127
    int gm0 = m0 + row0; if (gm0 > NNODES - 1) gm0 = NNODES - 1;
    int gm1 = m0 + row1; if (gm1 > NNODES - 1) gm1 = NNODES - 1;
    const __half* pA0 = g_xh + (size_t)gm0 * HDIM + c4 * 8;
    const __half* pA1 = g_xh + (size_t)gm1 * HDIM + c4 * 8;
    const __half* pB0 = g_Wh + (size_t)(n0 + row0) * HDIM + c4 * 8;
    const __half* pB1 = g_Wh + (size_t)(n0 + row1) * HDIM + c4 * 8;

    unsigned smA[NSTAGE], smB[NSTAGE];
    #pragma unroll
    for (int st = 0; st < NSTAGE; st++) {
        smA[st] = (unsigned)__cvta_generic_to_shared(sA + st * STAGE_H);
        smB[st] = (unsigned)__cvta_generic_to_shared(sB + st * STAGE_H);
    }

    // ldmatrix per-lane offsets (bytes within tile)
    const int aRow = wm + (lane & 15);                         // + mi*16
    const unsigned aKB = (unsigned)(lane >> 4) * 16u;          // 0 or 16
    const int bRow = wn + ((lane >> 4) & 1) * 8 + (lane & 7);  // + p*16
    const unsigned bKB = (unsigned)((lane >> 3) & 1) * 16u;    // 0 or 16

    float acc[4][4][4];
    #pragma unroll
    for (int i = 0; i < 4; i++)
        #pragma unroll
        for (int j = 0; j < 4; j++)
            #pragma unroll
            for (int v = 0; v < 4; v++) acc[i][j][v] = 0.f;

    // ---- prologue: prefetch stages 0 and 1 ----
    #pragma unroll
    for (int st = 0; st < 2; st++) {
        const int kt = st * BK;
        cp_async16(sA + st * STAGE_H + row0 * LDH + c4 * 8, pA0 + kt);
        cp_async16(sA + st * STAGE_H + row1 * LDH + c4 * 8, pA1 + kt);
        cp_async16(sB + st * STAGE_H + row0 * LDH + c4 * 8, pB0 + kt);
        cp_async16(sB + st * STAGE_H + row1 * LDH + c4 * 8, pB1 + kt);
        CP_COMMIT;
    }

    const int NIT = HDIM / BK;  // 24
    int s = 0;
    for (int it = 0; it < NIT; ++it) {
        if (it < NIT - 1) { CP_WAIT1; } else { CP_WAIT0; }
        __syncthreads();

        // prefetch stage it+2
        if (it + 2 < NIT) {
            const int st = (it + 2) % NSTAGE;
            const int kt = (it + 2) * BK;
            cp_async16(sA + st * STAGE_H + row0 * LDH + c4 * 8, pA0 + kt);
            cp_async16(sA + st * STAGE_H + row1 * LDH + c4 * 8, pA1 + kt);
            cp_async16(sB + st * STAGE_H + row0 * LDH + c4 * 8, pB0 + kt);
            cp_async16(sB + st * STAGE_H + row1 * LDH + c4 * 8, pB1 + kt);
            CP_COMMIT;
        }

        const unsigned bA = smA[s];
        const unsigned bB = smB[s];
        // ---- compute: 2 k=16 steps ----
        #pragma unroll
        for (int kk = 0; kk < 2; kk++) {
            unsigned af[4][4], bf[4][2];
            #pragma unroll
            for (int mi = 0; mi < 4; mi++) {
                unsigned addr = bA + (unsigned)(aRow + mi * 16) * (LDH * 2)
                              + (unsigned)kk * 32u + aKB;
                ldsm_x4(af[mi][0], af[mi][1], af[mi][2], af[mi][3], addr);
            }
            #pragma unroll
            for (int p = 0; p < 2; p++) {
                unsigned addr = bB + (unsigned)(bRow + p * 16) * (LDH * 2)
                              + (unsigned)kk * 32u + bKB;
                ldsm_x4(bf[2 * p][0], bf[2 * p][1], bf[2 * p + 1][0], bf[2 * p + 1][1], addr);
            }
            #pragma unroll
            for (int mi = 0; mi < 4; mi++)
                #pragma unroll
                for (int ni = 0; ni < 4; ni++)
                    MMA_F16(acc[mi][ni], af[mi], bf[ni]);
        }
        s = (s + 1 == NSTAGE) ? 0 : s + 1;
    }

    // ---- store to fp16 AB ----
    const int g  = lane >> 2;
    const int tg = lane & 3;
    #pragma unroll
    for (int mi = 0; mi < 4; mi++) {
        #pragma unroll
        for (int ni = 0; ni < 4; ni++) {
            const int gm = m0 + wm + mi * 16 + g;
            const int gn = n0 + wn + ni * 8 + 2 * tg;
            if (gm < NNODES) {
                *(__half2*)(g_AB + (size_t)gm * NOUT + gn) =
                    __floats2half2_rn(acc[mi][ni][0], acc[mi][ni][1]);
            }
            if (gm + 8 < NNODES) {
                *(__half2*)(g_AB + (size_t)(gm + 8) * NOUT + gn) =
                    __floats2half2_rn(acc[mi][ni][2], acc[mi][ni][3]);
            }
        }
    }
}

// ---------------------------------------------------------------------------
// Kernel 2: per-edge MLP tail. 2 edges per warp; 4 gathers in flight.
// ---------------------------------------------------------------------------
__global__ __launch_bounds__(256) void edge_kernel(const float* __restrict__ b1,
                                                   const float* __restrict__ W2,
                                                   const float* __restrict__ b2,
                                                   const float* __restrict__ cw,
                                                   const int* __restrict__ esrc,
                                                   const int* __restrict__ edst,
                                                   const int* __restrict__ labels,
                                                   float* __restrict__ out)
{
    __shared__ float s_b1[D1DIM];
    __shared__ float s_W2[2 * D1DIM];
    __shared__ float s_wn[EDGE_WARPS];
    __shared__ float s_w[EDGE_WARPS];

    const int tid  = threadIdx.x;
    const int lane = tid & 31;
    const int warp = tid >> 5;

    if (tid < D1DIM) s_b1[tid] = b1[tid];
    s_W2[tid]       = W2[tid];
    s_W2[tid + 256] = W2[tid + 256];
    __syncthreads();

    const int e0 = blockIdx.x * EDGES_PER_BLOCK + warp * EDGES_PER_WARP;
    const int e1 = e0 + 1;
    const int j0 = lane * 8;

    const int s0 = esrc[e0], d0 = edst[e0];
    const int s1 = esrc[e1], d1 = edst[e1];
    const uint4 va0 = *(const uint4*)(g_AB + (size_t)s0 * NOUT + j0);
    const uint4 vb0 = *(const uint4*)(g_AB + (size_t)d0 * NOUT + D1DIM + j0);
    const uint4 va1 = *(const uint4*)(g_AB + (size_t)s1 * NOUT + j0);
    const uint4 vb1 = *(const uint4*)(g_AB + (size_t)d1 * NOUT + D1DIM + j0);

    float a00 = 0.f, a01 = 0.f, a10 = 0.f, a11 = 0.f;
    {
        const __half2* ha0 = (const __half2*)&va0;
        const __half2* hb0 = (const __half2*)&vb0;
        const __half2* ha1 = (const __half2*)&va1;
        const __half2* hb1 = (const __half2*)&vb1;
        #pragma unroll
        for (int t = 0; t < 4; t++) {
            const int j = j0 + 2 * t;
            const float w0a = s_W2[j],       w0b = s_W2[j + 1];
            const float w1a = s_W2[256 + j], w1b = s_W2[256 + j + 1];
            const float bja = s_b1[j], bjb = s_b1[j + 1];
            {
                const float2 fa = __half22float2(ha0[t]);
                const float2 fb = __half22float2(hb0[t]);
                float v0 = fa.x + fb.x + bja;
                float h0 = 0.5f * v0 * (1.0f + erff(v0 * 0.70710678118654752f));
                a00 = fmaf(h0, w0a, a00); a01 = fmaf(h0, w1a, a01);
                float v1 = fa.y + fb.y + bjb;
                float h1 = 0.5f * v1 * (1.0f + erff(v1 * 0.70710678118654752f));
                a00 = fmaf(h1, w0b, a00); a01 = fmaf(h1, w1b, a01);
            }
            {
                const float2 fa = __half22float2(ha1[t]);
                const float2 fb = __half22float2(hb1[t]);
                float v0 = fa.x + fb.x + bja;
                float h0 = 0.5f * v0 * (1.0f + erff(v0 * 0.70710678118654752f));
                a10 = fmaf(h0, w0a, a10); a11 = fmaf(h0, w1a, a11);
                float v1 = fa.y + fb.y + bjb;
                float h1 = 0.5f * v1 * (1.0f + erff(v1 * 0.70710678118654752f));
                a10 = fmaf(h1, w0b, a10); a11 = fmaf(h1, w1b, a11);
            }
        }
    }
    #pragma unroll
    for (int o = 16; o > 0; o >>= 1) {
        a00 += __shfl_xor_sync(0xFFFFFFFFu, a00, o);
        a01 += __shfl_xor_sync(0xFFFFFFFFu, a01, o);
        a10 += __shfl_xor_sync(0xFFFFFFFFu, a10, o);
        a11 += __shfl_xor_sync(0xFFFFFFFFu, a11, o);
    }

    float wn = 0.f, wsum = 0.f;
    if (lane == 0) {
        const float bb0 = __ldg(&b2[0]);
        const float bb1 = __ldg(&b2[1]);
        {
            const float l0 = a00 + bb0, l1 = a01 + bb1;
            const float m  = fmaxf(l0, l1);
            const float x0 = expf(l0 - m), x1 = expf(l1 - m);
            const float ssum = x0 + x1, inv = 1.0f / ssum;
            out[1 + 2 * e0]     = x0 * inv;
            out[1 + 2 * e0 + 1] = x1 * inv;
            const int lb = labels[e0];
            const float logp = ((lb ? l1 : l0) - m) - logf(ssum);
            const float w = __ldg(&cw[lb]);
            wn += -w * logp; wsum += w;
        }
        {
            const float l0 = a10 + bb0, l1 = a11 + bb1;
            const float m  = fmaxf(l0, l1);
            const float x0 = expf(l0 - m), x1 = expf(l1 - m);
            const float ssum = x0 + x1, inv = 1.0f / ssum;
            out[1 + 2 * e1]     = x0 * inv;
            out[1 + 2 * e1 + 1] = x1 * inv;
            const int lb = labels[e1];
            const float logp = ((lb ? l1 : l0) - m) - logf(ssum);
            const float w = __ldg(&cw[lb]);
            wn += -w * logp; wsum += w;
        }
        s_wn[warp] = wn; s_w[warp] = wsum;
    }
    __syncthreads();
    if (tid == 0) {
        float a = 0.f, b = 0.f;
        #pragma unroll
        for (int i = 0; i < EDGE_WARPS; i++) { a += s_wn[i]; b += s_w[i]; }
        g_partials[blockIdx.x]               = a;
        g_partials[EDGE_BLOCKS + blockIdx.x] = b;
    }
}

// ---------------------------------------------------------------------------
// Kernel 3: deterministic final reduction -> loss at out[0]
// ---------------------------------------------------------------------------
__global__ __launch_bounds__(256) void finalize_kernel(float* __restrict__ out)
{
    __shared__ float sa[256];
    __shared__ float sb[256];
    const int tid = threadIdx.x;
    float a = 0.f, b = 0.f;
    for (int i = tid; i < EDGE_BLOCKS; i += 256) {
        a += g_partials[i];
        b += g_partials[EDGE_BLOCKS + i];
    }
    sa[tid] = a; sb[tid] = b;
    __syncthreads();
    for (int o = 128; o > 0; o >>= 1) {
        if (tid < o) { sa[tid] += sa[tid + o]; sb[tid] += sb[tid + o]; }
        __syncthreads();
    }
    if (tid == 0) out[0] = sa[0] / sb[0];
}

// ---------------------------------------------------------------------------
extern "C" void kernel_launch(void* const* d_in, const int* in_sizes, int n_in,
                              void* d_out, int out_size)
{
    const float* x      = (const float*)d_in[0];
    const float* W1     = (const float*)d_in[1];
    const float* b1     = (const float*)d_in[2];
    const float* W2     = (const float*)d_in[3];
    const float* b2     = (const float*)d_in[4];
    const float* cw     = (const float*)d_in[5];
    const int*   esrc   = (const int*)d_in[6];
    const int*   edst   = (const int*)d_in[7];
    const int*   labels = (const int*)d_in[8];
    float* out = (float*)d_out;

    const int GEMM_SMEM = 2 * NSTAGE * STAGE_H * (int)sizeof(__half);  // 61440
    cudaFuncSetAttribute(gemm_kernel,
                         cudaFuncAttributeMaxDynamicSharedMemorySize, GEMM_SMEM);

    const int nx4 = (int)(((size_t)NNODES * HDIM / 4 + 255) / 256);   // 37500
    conv_x_kernel<<<nx4, 256>>>(x);
    conv_w_kernel<<<(NOUT * HDIM / 4 + 255) / 256, 256>>>(W1);

    dim3 ggrid((NNODES + BM - 1) / BM, NOUT / BN);   // 391 x 4
    gemm_kernel<<<ggrid, 256, GEMM_SMEM>>>();
    edge_kernel<<<EDGE_BLOCKS, 256>>>(b1, W2, b2, cw, esrc, edst, labels, out);
    finalize_kernel<<<1, 256>>>(out);
}